// round 2
// baseline (speedup 1.0000x reference)
#include <cuda_runtime.h>
#include <math.h>

#define STATE_DIM 64
#define HID 512
#define ACT 8
#define BATCH 128
#define SEQ 16
#define TSTEPS (SEQ*BATCH)   // 2048 sequential LSTM steps
#define G4 (4*HID)
#define N0 64                // CTAs for layer-0 chain
#define N1 64                // CTAs for layer-1 chain
#define NCTA (N0+N1)
#define TPB 512

// ---------------- scratch ---------------------------------------------------
__device__ float    g_x [BATCH*HID];
__device__ float    g_A0[BATCH*G4];
__device__ float    g_h0[TSTEPS*HID];
__device__ float    g_h1[TSTEPS*HID];
__device__ unsigned g_done0[TSTEPS*N0];   // per-(step, producer-CTA) flags
__device__ unsigned g_done1[TSTEPS*N1];

// ---------------- helpers ---------------------------------------------------
__device__ __forceinline__ float sigf(float x) { return 1.f/(1.f+__expf(-x)); }
__device__ __forceinline__ float tanhfast(float x) { return 2.f*sigf(2.f*x) - 1.f; }

__device__ __forceinline__ uint4 ldv4(const uint4* p) {
    uint4 v;
    asm volatile("ld.volatile.global.v4.u32 {%0,%1,%2,%3}, [%4];"
                 : "=r"(v.x), "=r"(v.y), "=r"(v.z), "=r"(v.w) : "l"(p) : "memory");
    return v;
}
__device__ __forceinline__ unsigned long long pk(float a, float b) {
    unsigned long long r;
    asm("mov.b64 %0, {%1,%2};" : "=l"(r) : "f"(a), "f"(b));
    return r;
}
__device__ __forceinline__ unsigned long long fma2(unsigned long long a,
                                                   unsigned long long b,
                                                   unsigned long long c) {
    unsigned long long d;
    asm("fma.rn.f32x2 %0, %1, %2, %3;" : "=l"(d) : "l"(a), "l"(b), "l"(c));
    return d;
}
__device__ __forceinline__ float fsum(unsigned long long v) {
    float x, y;
    asm("mov.b64 {%0,%1}, %2;" : "=f"(x), "=f"(y) : "l"(v));
    return x + y;
}

// ---------------- K0: reset flags (graph replays) ---------------------------
__global__ void k_init() {
    int i = blockIdx.x*blockDim.x + threadIdx.x;
    if (i < TSTEPS*N0) { g_done0[i] = 0u; g_done1[i] = 0u; }
}

// ---------------- K1: LayerNorm + pre-linear --------------------------------
__global__ void k_pre(const float* __restrict__ state, const float* __restrict__ lng,
                      const float* __restrict__ lnb,   const float* __restrict__ Wpre,
                      const float* __restrict__ bpre) {
    __shared__ float xn[STATE_DIM];
    __shared__ float stats[2];
    int b = blockIdx.x, tid = threadIdx.x;
    if (tid < STATE_DIM) xn[tid] = state[b*STATE_DIM + tid];
    __syncthreads();
    if (tid == 0) {
        float mu = 0.f;
        for (int k = 0; k < STATE_DIM; k++) mu += xn[k];
        mu *= (1.f/STATE_DIM);
        float var = 0.f;
        for (int k = 0; k < STATE_DIM; k++) { float d = xn[k]-mu; var += d*d; }
        var *= (1.f/STATE_DIM);
        stats[0] = mu; stats[1] = rsqrtf(var + 1e-5f);
    }
    __syncthreads();
    float mu = stats[0], rs = stats[1];
    if (tid < STATE_DIM) xn[tid] = (xn[tid]-mu)*rs*lng[tid] + lnb[tid];
    __syncthreads();
    float acc = bpre[tid];
    const float* w = Wpre + tid*STATE_DIM;
    #pragma unroll 16
    for (int k = 0; k < STATE_DIM; k++) acc = fmaf(w[k], xn[k], acc);
    g_x[b*HID + tid] = acc;
}

// ---------------- K2: A0 = W_ih0@x + b_ih0 + b_hh0 --------------------------
__global__ void k_a0(const float* __restrict__ Wih, const float* __restrict__ bih,
                     const float* __restrict__ bhh) {
    int tid = threadIdx.x, lane = tid & 31, warp = tid >> 5;
    int row = blockIdx.x*8 + warp;
    float wr[16];
    const float* w = Wih + (size_t)row*HID + lane*16;
    #pragma unroll
    for (int i = 0; i < 16; i++) wr[i] = w[i];
    float bsum = bih[row] + bhh[row];
    __shared__ float xs[HID];
    for (int b = 0; b < BATCH; b++) {
        __syncthreads();
        for (int i = tid; i < HID; i += 256) xs[i] = g_x[b*HID + i];
        __syncthreads();
        float a = 0.f;
        #pragma unroll
        for (int i = 0; i < 16; i++) a = fmaf(wr[i], xs[lane*16 + i], a);
        #pragma unroll
        for (int o = 16; o > 0; o >>= 1) a += __shfl_xor_sync(0xffffffffu, a, o);
        if (lane == 0) g_A0[b*G4 + row] = a + bsum;
    }
}

// ---------------- K_LSTM: persistent, two pipelined groups ------------------
// Sync: per-producer-CTA flag words (no atomics), per-warp fine-grained polls,
// 2 barriers/step. Matvec: FFMA2 (fp32x2) fed from LDS.128.
__global__ void __launch_bounds__(TPB, 1)
k_lstm(const float* __restrict__ Wih, const float* __restrict__ Whh,
       const float* __restrict__ bih, const float* __restrict__ bhh) {
    __shared__ float hbuf[2*HID];
    __shared__ float red[16*33];
    __shared__ float As[BATCH*32];
    __shared__ float bias1[32];
    const int tid = threadIdx.x, lane = tid & 31, warp = tid >> 5;
    const int gt = lane >> 3, j = lane & 7;
    float c_state = 0.f;

    if (blockIdx.x < N0) {
        // ===================== layer-0 group =====================
        const int g = blockIdx.x;
        const int grow = gt*HID + g*8 + j;
        unsigned long long w2[16];                 // 32 cols [warp*32, +32)
        {
            const float4* wp = (const float4*)(Whh + (size_t)grow*HID + warp*32);
            #pragma unroll
            for (int i = 0; i < 8; i++) {
                float4 v = wp[i];
                w2[2*i]   = pk(v.x, v.y);
                w2[2*i+1] = pk(v.z, v.w);
            }
        }
        for (int i = tid; i < BATCH*32; i += TPB) {
            int bb = i >> 5, lr = i & 31;
            As[i] = g_A0[bb*G4 + (lr>>3)*HID + g*8 + (lr&7)];
        }
        __syncthreads();

        for (int t = 0; t < TSTEPS; t++) {
            if (t > 0) {
                // warp needs h0[t-1] cols [warp*32, +32) -> producers warp*4..+3
                const uint4* fp = (const uint4*)(g_done0 + (size_t)(t-1)*N0 + warp*4);
                for (;;) { uint4 a = ldv4(fp); if (a.x & a.y & a.z & a.w) break; }
                __threadfence();
                hbuf[warp*32 + lane] = g_h0[(size_t)(t-1)*HID + warp*32 + lane];
            } else {
                hbuf[warp*32 + lane] = 0.f;
            }
            __syncthreads();
            unsigned long long a0 = 0ull, a1 = 0ull;
            const float4* hp = (const float4*)(hbuf + warp*32);
            #pragma unroll
            for (int i = 0; i < 8; i++) {
                float4 v = hp[i];
                a0 = fma2(w2[2*i],   pk(v.x, v.y), a0);
                a1 = fma2(w2[2*i+1], pk(v.z, v.w), a1);
            }
            red[warp*33 + lane] = fsum(a0) + fsum(a1);
            __syncthreads();
            if (warp == 0) {
                float gv = As[(t & (BATCH-1))*32 + lane];
                #pragma unroll
                for (int ww = 0; ww < 16; ww++) gv += red[ww*33 + lane];
                float vi = __shfl_sync(0xffffffffu, gv, j);
                float vf = __shfl_sync(0xffffffffu, gv, 8 + j);
                float vg = __shfl_sync(0xffffffffu, gv, 16 + j);
                float vo = __shfl_sync(0xffffffffu, gv, 24 + j);
                if (lane < 8) {
                    c_state = sigf(vf)*c_state + sigf(vi)*tanhfast(vg);
                    g_h0[(size_t)t*HID + g*8 + lane] = sigf(vo)*tanhfast(c_state);
                }
                __syncwarp();
                if (lane == 0) {
                    __threadfence();
                    *(volatile unsigned*)&g_done0[(size_t)t*N0 + g] = 1u;
                }
            }
        }
    } else {
        // ===================== layer-1 group =====================
        const int g = blockIdx.x - N0;
        const int grow = gt*HID + g*8 + j;
        unsigned long long w2[32];                 // 64 cols [warp*64, +64)
        {                                          // over [h0_t | h1_{t-1}]
            const float4* wp = (warp < 8)
                ? (const float4*)(Wih + (size_t)G4*HID + (size_t)grow*HID + warp*64)
                : (const float4*)(Whh + (size_t)G4*HID + (size_t)grow*HID + (warp-8)*64);
            #pragma unroll
            for (int i = 0; i < 16; i++) {
                float4 v = wp[i];
                w2[2*i]   = pk(v.x, v.y);
                w2[2*i+1] = pk(v.z, v.w);
            }
        }
        if (tid < 32)
            bias1[tid] = bih[G4 + (tid>>3)*HID + g*8 + (tid&7)]
                       + bhh[G4 + (tid>>3)*HID + g*8 + (tid&7)];
        __syncthreads();

        for (int t = 0; t < TSTEPS; t++) {
            if (warp < 8) {
                // needs h0[t] cols [warp*64, +64) -> producers warp*8..+7
                const uint4* fp = (const uint4*)(g_done0 + (size_t)t*N0 + warp*8);
                for (;;) {
                    uint4 a = ldv4(fp), b = ldv4(fp+1);
                    if (a.x & a.y & a.z & a.w & b.x & b.y & b.z & b.w) break;
                }
                __threadfence();
                float2 hv = *(const float2*)(g_h0 + (size_t)t*HID + warp*64 + 2*lane);
                *(float2*)(hbuf + warp*64 + 2*lane) = hv;
            } else {
                if (t > 0) {
                    const uint4* fp = (const uint4*)(g_done1 + (size_t)(t-1)*N1 + (warp-8)*8);
                    for (;;) {
                        uint4 a = ldv4(fp), b = ldv4(fp+1);
                        if (a.x & a.y & a.z & a.w & b.x & b.y & b.z & b.w) break;
                    }
                    __threadfence();
                    float2 hv = *(const float2*)(g_h1 + (size_t)(t-1)*HID + (warp-8)*64 + 2*lane);
                    *(float2*)(hbuf + warp*64 + 2*lane) = hv;   // HID + (warp-8)*64 == warp*64
                } else {
                    *(float2*)(hbuf + warp*64 + 2*lane) = make_float2(0.f, 0.f);
                }
            }
            __syncthreads();
            unsigned long long a0 = 0ull, a1 = 0ull;
            const float4* hp = (const float4*)(hbuf + warp*64);
            #pragma unroll
            for (int i = 0; i < 16; i++) {
                float4 v = hp[i];
                a0 = fma2(w2[2*i],   pk(v.x, v.y), a0);
                a1 = fma2(w2[2*i+1], pk(v.z, v.w), a1);
            }
            red[warp*33 + lane] = fsum(a0) + fsum(a1);
            __syncthreads();
            if (warp == 0) {
                float gv = bias1[lane];
                #pragma unroll
                for (int ww = 0; ww < 16; ww++) gv += red[ww*33 + lane];
                float vi = __shfl_sync(0xffffffffu, gv, j);
                float vf = __shfl_sync(0xffffffffu, gv, 8 + j);
                float vg = __shfl_sync(0xffffffffu, gv, 16 + j);
                float vo = __shfl_sync(0xffffffffu, gv, 24 + j);
                if (lane < 8) {
                    c_state = sigf(vf)*c_state + sigf(vi)*tanhfast(vg);
                    g_h1[(size_t)t*HID + g*8 + lane] = sigf(vo)*tanhfast(c_state);
                }
                __syncwarp();
                if (lane == 0) {
                    __threadfence();
                    *(volatile unsigned*)&g_done1[(size_t)t*N1 + g] = 1u;
                }
            }
        }
    }
}

// ---------------- K3: final FC + tanh ---------------------------------------
__global__ void k_fc(const float* __restrict__ Wfc, const float* __restrict__ bfc,
                     float* __restrict__ out) {
    int s = blockIdx.x;
    int tid = threadIdx.x, lane = tid & 31, a = tid >> 5;
    int tt = s >> 7, b = s & 127;
    const float* h = g_h1 + (size_t)s*HID;
    const float* w = Wfc + a*HID;
    float acc = 0.f;
    for (int k = lane; k < HID; k += 32) acc = fmaf(h[k], w[k], acc);
    #pragma unroll
    for (int o = 16; o > 0; o >>= 1) acc += __shfl_xor_sync(0xffffffffu, acc, o);
    if (lane == 0) out[b*(SEQ*ACT) + tt*ACT + a] = tanhf(acc + bfc[a]);
}

// ---------------------------------------------------------------------------
extern "C" void kernel_launch(void* const* d_in, const int* in_sizes, int n_in,
                              void* d_out, int out_size) {
    const float* state = (const float*)d_in[0];
    const float* lng   = (const float*)d_in[1];
    const float* lnb   = (const float*)d_in[2];
    const float* Wpre  = (const float*)d_in[3];
    const float* bpre  = (const float*)d_in[4];
    const float* Wih   = (const float*)d_in[5];
    const float* Whh   = (const float*)d_in[6];
    const float* bih   = (const float*)d_in[7];
    const float* bhh   = (const float*)d_in[8];
    const float* Wfc   = (const float*)d_in[9];
    const float* bfc   = (const float*)d_in[10];
    float* out = (float*)d_out;

    k_init<<<(TSTEPS*N0 + 255)/256, 256>>>();
    k_pre <<<BATCH, TPB>>>(state, lng, lnb, Wpre, bpre);
    k_a0  <<<G4/8, 256>>>(Wih, bih, bhh);
    k_lstm<<<NCTA, TPB>>>(Wih, Whh, bih, bhh);
    k_fc  <<<TSTEPS, 256>>>(Wfc, bfc, out);
}

// round 3
// speedup vs baseline: 2.7027x; 2.7027x over previous
#include <cuda_runtime.h>
#include <math.h>

#define STATE_DIM 64
#define HID 512
#define ACT 8
#define BATCH 128
#define SEQ 16
#define TSTEPS (SEQ*BATCH)   // 2048 sequential LSTM steps
#define G4 (4*HID)
#define N0 64
#define N1 64
#define NCTA (N0+N1)
#define TPB 512

// ---------------- scratch ---------------------------------------------------
__device__ float    g_x [BATCH*HID];
__device__ float    g_A0[BATCH*G4];
__device__ float    g_h0[TSTEPS*HID];
__device__ float    g_h1[TSTEPS*HID];
__device__ unsigned g_done0[TSTEPS*N0];   // packed per-(step,CTA) flags
__device__ unsigned g_done1[TSTEPS*N1];

// ---------------- helpers ---------------------------------------------------
__device__ __forceinline__ float tanhapx(float x) {
    float y; asm("tanh.approx.f32 %0, %1;" : "=f"(y) : "f"(x)); return y;
}
__device__ __forceinline__ float sigf(float x) { return 0.5f*tanhapx(0.5f*x) + 0.5f; }

__device__ __forceinline__ unsigned long long ld_acq64(const unsigned long long* p) {
    unsigned long long v;
    asm volatile("ld.acquire.gpu.global.u64 %0, [%1];" : "=l"(v) : "l"(p) : "memory");
    return v;
}
__device__ __forceinline__ void st_rel32(unsigned* p, unsigned v) {
    asm volatile("st.release.gpu.global.u32 [%0], %1;" :: "l"(p), "r"(v) : "memory");
}
__device__ __forceinline__ unsigned long long fma2(unsigned long long a,
                                                   unsigned long long b,
                                                   unsigned long long c) {
    unsigned long long d;
    asm("fma.rn.f32x2 %0, %1, %2, %3;" : "=l"(d) : "l"(a), "l"(b), "l"(c));
    return d;
}
__device__ __forceinline__ float fsum(unsigned long long v) {
    float x, y;
    asm("mov.b64 {%0,%1}, %2;" : "=f"(x), "=f"(y) : "l"(v));
    return x + y;
}
#define BOTH1 0x0000000100000001ull

// ---------------- K0: reset flags (graph replays) ---------------------------
__global__ void k_init() {
    int i = blockIdx.x*blockDim.x + threadIdx.x;
    if (i < TSTEPS*N0) { g_done0[i] = 0u; g_done1[i] = 0u; }
}

// ---------------- K1: LayerNorm + pre-linear --------------------------------
__global__ void k_pre(const float* __restrict__ state, const float* __restrict__ lng,
                      const float* __restrict__ lnb,   const float* __restrict__ Wpre,
                      const float* __restrict__ bpre) {
    __shared__ float xn[STATE_DIM];
    __shared__ float stats[2];
    int b = blockIdx.x, tid = threadIdx.x;
    if (tid < STATE_DIM) xn[tid] = state[b*STATE_DIM + tid];
    __syncthreads();
    if (tid == 0) {
        float mu = 0.f;
        for (int k = 0; k < STATE_DIM; k++) mu += xn[k];
        mu *= (1.f/STATE_DIM);
        float var = 0.f;
        for (int k = 0; k < STATE_DIM; k++) { float d = xn[k]-mu; var += d*d; }
        var *= (1.f/STATE_DIM);
        stats[0] = mu; stats[1] = rsqrtf(var + 1e-5f);
    }
    __syncthreads();
    float mu = stats[0], rs = stats[1];
    if (tid < STATE_DIM) xn[tid] = (xn[tid]-mu)*rs*lng[tid] + lnb[tid];
    __syncthreads();
    float acc = bpre[tid];
    const float* w = Wpre + tid*STATE_DIM;
    #pragma unroll 16
    for (int k = 0; k < STATE_DIM; k++) acc = fmaf(w[k], xn[k], acc);
    g_x[b*HID + tid] = acc;
}

// ---------------- K2: A0 = W_ih0@x + b_ih0 + b_hh0 --------------------------
__global__ void k_a0(const float* __restrict__ Wih, const float* __restrict__ bih,
                     const float* __restrict__ bhh) {
    int tid = threadIdx.x, lane = tid & 31, warp = tid >> 5;
    int row = blockIdx.x*8 + warp;
    float wr[16];
    const float* w = Wih + (size_t)row*HID + lane*16;
    #pragma unroll
    for (int i = 0; i < 16; i++) wr[i] = w[i];
    float bsum = bih[row] + bhh[row];
    __shared__ float xs[HID];
    for (int b = 0; b < BATCH; b++) {
        __syncthreads();
        for (int i = tid; i < HID; i += 256) xs[i] = g_x[b*HID + i];
        __syncthreads();
        float a = 0.f;
        #pragma unroll
        for (int i = 0; i < 16; i++) a = fmaf(wr[i], xs[lane*16 + i], a);
        #pragma unroll
        for (int o = 16; o > 0; o >>= 1) a += __shfl_xor_sync(0xffffffffu, a, o);
        if (lane == 0) g_A0[b*G4 + row] = a + bsum;
    }
}

// ---------------- K_LSTM: persistent, two pipelined groups ------------------
// Sync: packed per-CTA flags; warp0-only acquire-poll (1 u64/lane + ballot);
// producer release-store. h read directly via uniform LDG (no smem staging).
__global__ void __launch_bounds__(TPB, 1)
k_lstm(const float* __restrict__ Wih, const float* __restrict__ Whh,
       const float* __restrict__ bih, const float* __restrict__ bhh) {
    __shared__ float red[16*33];
    __shared__ float As[BATCH*32];
    __shared__ float bias1[32];
    const int tid = threadIdx.x, lane = tid & 31, warp = tid >> 5;
    const int gt = lane >> 3, j = lane & 7;
    float c_state = 0.f;

    if (blockIdx.x < N0) {
        // ===================== layer-0 group =====================
        const int g = blockIdx.x;
        const int grow = gt*HID + g*8 + j;
        unsigned long long w2[16];                 // 32 cols [warp*32,+32)
        {
            const ulonglong2* wp = (const ulonglong2*)(Whh + (size_t)grow*HID + warp*32);
            #pragma unroll
            for (int i = 0; i < 8; i++) { ulonglong2 v = wp[i]; w2[2*i] = v.x; w2[2*i+1] = v.y; }
        }
        for (int i = tid; i < BATCH*32; i += TPB) {
            int bb = i >> 5, lr = i & 31;
            As[i] = g_A0[bb*G4 + (lr>>3)*HID + g*8 + (lr&7)];
        }
        __syncthreads();

        for (int t = 0; t < TSTEPS; t++) {
            if (t > 0 && warp == 0) {
                const unsigned long long* fp =
                    (const unsigned long long*)(g_done0 + (size_t)(t-1)*N0) + lane;
                while (!__all_sync(0xffffffffu, ld_acq64(fp) == BOTH1)) {}
            }
            __syncthreads();
            unsigned long long a0 = 0ull, a1 = 0ull;
            if (t > 0) {
                const ulonglong2* hp =
                    (const ulonglong2*)(g_h0 + (size_t)(t-1)*HID + warp*32);
                #pragma unroll
                for (int i = 0; i < 8; i++) {
                    ulonglong2 v = hp[i];
                    a0 = fma2(w2[2*i],   v.x, a0);
                    a1 = fma2(w2[2*i+1], v.y, a1);
                }
            }
            red[warp*33 + lane] = fsum(a0) + fsum(a1);
            __syncthreads();
            if (warp == 0) {
                float gv = As[(t & (BATCH-1))*32 + lane];
                #pragma unroll
                for (int ww = 0; ww < 16; ww++) gv += red[ww*33 + lane];
                float vi = __shfl_sync(0xffffffffu, gv, j);
                float vf = __shfl_sync(0xffffffffu, gv, 8 + j);
                float vg = __shfl_sync(0xffffffffu, gv, 16 + j);
                float vo = __shfl_sync(0xffffffffu, gv, 24 + j);
                if (lane < 8) {
                    c_state = sigf(vf)*c_state + sigf(vi)*tanhapx(vg);
                    g_h0[(size_t)t*HID + g*8 + lane] = sigf(vo)*tanhapx(c_state);
                }
                __syncwarp();
                if (lane == 0) st_rel32(&g_done0[(size_t)t*N0 + g], 1u);
            }
        }
    } else {
        // ===================== layer-1 group =====================
        const int g = blockIdx.x - N0;
        const int grow = gt*HID + g*8 + j;
        unsigned long long w2[32];                 // 64 cols [warp*64,+64) of [h0|h1]
        {
            const ulonglong2* wp = (warp < 8)
                ? (const ulonglong2*)(Wih + (size_t)G4*HID + (size_t)grow*HID + warp*64)
                : (const ulonglong2*)(Whh + (size_t)G4*HID + (size_t)grow*HID + (warp-8)*64);
            #pragma unroll
            for (int i = 0; i < 16; i++) { ulonglong2 v = wp[i]; w2[2*i] = v.x; w2[2*i+1] = v.y; }
        }
        if (tid < 32)
            bias1[tid] = bih[G4 + (tid>>3)*HID + g*8 + (tid&7)]
                       + bhh[G4 + (tid>>3)*HID + g*8 + (tid&7)];
        __syncthreads();

        for (int t = 0; t < TSTEPS; t++) {
            if (warp == 0) {
                const unsigned long long* fp0 =
                    (const unsigned long long*)(g_done0 + (size_t)t*N0) + lane;
                while (!__all_sync(0xffffffffu, ld_acq64(fp0) == BOTH1)) {}
                if (t > 0) {
                    const unsigned long long* fp1 =
                        (const unsigned long long*)(g_done1 + (size_t)(t-1)*N1) + lane;
                    while (!__all_sync(0xffffffffu, ld_acq64(fp1) == BOTH1)) {}
                }
            }
            __syncthreads();
            unsigned long long a0 = 0ull, a1 = 0ull, a2 = 0ull, a3 = 0ull;
            if (warp < 8) {
                const ulonglong2* hp =
                    (const ulonglong2*)(g_h0 + (size_t)t*HID + warp*64);
                #pragma unroll
                for (int i = 0; i < 8; i++) {
                    ulonglong2 v0 = hp[2*i], v1 = hp[2*i+1];
                    a0 = fma2(w2[4*i],   v0.x, a0);
                    a1 = fma2(w2[4*i+1], v0.y, a1);
                    a2 = fma2(w2[4*i+2], v1.x, a2);
                    a3 = fma2(w2[4*i+3], v1.y, a3);
                }
            } else if (t > 0) {
                const ulonglong2* hp =
                    (const ulonglong2*)(g_h1 + (size_t)(t-1)*HID + (warp-8)*64);
                #pragma unroll
                for (int i = 0; i < 8; i++) {
                    ulonglong2 v0 = hp[2*i], v1 = hp[2*i+1];
                    a0 = fma2(w2[4*i],   v0.x, a0);
                    a1 = fma2(w2[4*i+1], v0.y, a1);
                    a2 = fma2(w2[4*i+2], v1.x, a2);
                    a3 = fma2(w2[4*i+3], v1.y, a3);
                }
            }
            red[warp*33 + lane] = (fsum(a0) + fsum(a1)) + (fsum(a2) + fsum(a3));
            __syncthreads();
            if (warp == 0) {
                float gv = bias1[lane];
                #pragma unroll
                for (int ww = 0; ww < 16; ww++) gv += red[ww*33 + lane];
                float vi = __shfl_sync(0xffffffffu, gv, j);
                float vf = __shfl_sync(0xffffffffu, gv, 8 + j);
                float vg = __shfl_sync(0xffffffffu, gv, 16 + j);
                float vo = __shfl_sync(0xffffffffu, gv, 24 + j);
                if (lane < 8) {
                    c_state = sigf(vf)*c_state + sigf(vi)*tanhapx(vg);
                    g_h1[(size_t)t*HID + g*8 + lane] = sigf(vo)*tanhapx(c_state);
                }
                __syncwarp();
                if (lane == 0) st_rel32(&g_done1[(size_t)t*N1 + g], 1u);
            }
        }
    }
}

// ---------------- K3: final FC + tanh ---------------------------------------
__global__ void k_fc(const float* __restrict__ Wfc, const float* __restrict__ bfc,
                     float* __restrict__ out) {
    int s = blockIdx.x;
    int tid = threadIdx.x, lane = tid & 31, a = tid >> 5;
    int tt = s >> 7, b = s & 127;
    const float* h = g_h1 + (size_t)s*HID;
    const float* w = Wfc + a*HID;
    float acc = 0.f;
    for (int k = lane; k < HID; k += 32) acc = fmaf(h[k], w[k], acc);
    #pragma unroll
    for (int o = 16; o > 0; o >>= 1) acc += __shfl_xor_sync(0xffffffffu, acc, o);
    if (lane == 0) out[b*(SEQ*ACT) + tt*ACT + a] = tanhf(acc + bfc[a]);
}

// ---------------------------------------------------------------------------
extern "C" void kernel_launch(void* const* d_in, const int* in_sizes, int n_in,
                              void* d_out, int out_size) {
    const float* state = (const float*)d_in[0];
    const float* lng   = (const float*)d_in[1];
    const float* lnb   = (const float*)d_in[2];
    const float* Wpre  = (const float*)d_in[3];
    const float* bpre  = (const float*)d_in[4];
    const float* Wih   = (const float*)d_in[5];
    const float* Whh   = (const float*)d_in[6];
    const float* bih   = (const float*)d_in[7];
    const float* bhh   = (const float*)d_in[8];
    const float* Wfc   = (const float*)d_in[9];
    const float* bfc   = (const float*)d_in[10];
    float* out = (float*)d_out;

    k_init<<<(TSTEPS*N0 + 255)/256, 256>>>();
    k_pre <<<BATCH, TPB>>>(state, lng, lnb, Wpre, bpre);
    k_a0  <<<G4/8, 256>>>(Wih, bih, bhh);
    k_lstm<<<NCTA, TPB>>>(Wih, Whh, bih, bhh);
    k_fc  <<<TSTEPS, 256>>>(Wfc, bfc, out);
}

// round 4
// speedup vs baseline: 6.0027x; 2.2210x over previous
#include <cuda_runtime.h>
#include <math.h>

#define STATE_DIM 64
#define HID 512
#define ACT 8
#define BATCH 128
#define SEQ 16
#define TSTEPS (SEQ*BATCH)   // 2048 sequential LSTM steps
#define G4 (4*HID)
#define N0 64
#define N1 64
#define NCTA (N0+N1)
#define TPB 512

// ---------------- scratch ---------------------------------------------------
__device__ float    g_x [BATCH*HID];
__device__ float    g_A0[BATCH*G4];
__device__ float    g_h0[TSTEPS*HID];
__device__ float    g_h1[TSTEPS*HID];
__device__ unsigned g_flag0[TSTEPS];      // arrival counters per step
__device__ unsigned g_flag1[TSTEPS];

// ---------------- helpers ---------------------------------------------------
__device__ __forceinline__ float tanhapx(float x) {
    float y; asm("tanh.approx.f32 %0, %1;" : "=f"(y) : "f"(x)); return y;
}
__device__ __forceinline__ float sigf(float x) { return 0.5f*tanhapx(0.5f*x) + 0.5f; }

__device__ __forceinline__ unsigned ld_acq32(const unsigned* p) {
    unsigned v;
    asm volatile("ld.acquire.gpu.global.u32 %0, [%1];" : "=r"(v) : "l"(p) : "memory");
    return v;
}
__device__ __forceinline__ void red_rel_add(unsigned* p) {
    asm volatile("red.release.gpu.global.add.u32 [%0], %1;" :: "l"(p), "r"(1u) : "memory");
}
__device__ __forceinline__ unsigned long long fma2(unsigned long long a,
                                                   unsigned long long b,
                                                   unsigned long long c) {
    unsigned long long d;
    asm("fma.rn.f32x2 %0, %1, %2, %3;" : "=l"(d) : "l"(a), "l"(b), "l"(c));
    return d;
}
__device__ __forceinline__ float fsum(unsigned long long v) {
    float x, y;
    asm("mov.b64 {%0,%1}, %2;" : "=f"(x), "=f"(y) : "l"(v));
    return x + y;
}

// ---------------- K0: reset flags (graph replays) ---------------------------
__global__ void k_init() {
    int i = blockIdx.x*blockDim.x + threadIdx.x;
    if (i < TSTEPS) { g_flag0[i] = 0u; g_flag1[i] = 0u; }
}

// ---------------- K1: LayerNorm + pre-linear --------------------------------
__global__ void k_pre(const float* __restrict__ state, const float* __restrict__ lng,
                      const float* __restrict__ lnb,   const float* __restrict__ Wpre,
                      const float* __restrict__ bpre) {
    __shared__ float xn[STATE_DIM];
    __shared__ float stats[2];
    int b = blockIdx.x, tid = threadIdx.x;
    if (tid < STATE_DIM) xn[tid] = state[b*STATE_DIM + tid];
    __syncthreads();
    if (tid == 0) {
        float mu = 0.f;
        for (int k = 0; k < STATE_DIM; k++) mu += xn[k];
        mu *= (1.f/STATE_DIM);
        float var = 0.f;
        for (int k = 0; k < STATE_DIM; k++) { float d = xn[k]-mu; var += d*d; }
        var *= (1.f/STATE_DIM);
        stats[0] = mu; stats[1] = rsqrtf(var + 1e-5f);
    }
    __syncthreads();
    float mu = stats[0], rs = stats[1];
    if (tid < STATE_DIM) xn[tid] = (xn[tid]-mu)*rs*lng[tid] + lnb[tid];
    __syncthreads();
    float acc = bpre[tid];
    const float* w = Wpre + tid*STATE_DIM;
    #pragma unroll 16
    for (int k = 0; k < STATE_DIM; k++) acc = fmaf(w[k], xn[k], acc);
    g_x[b*HID + tid] = acc;
}

// ---------------- K2: A0 = W_ih0@x + b_ih0 + b_hh0 --------------------------
__global__ void k_a0(const float* __restrict__ Wih, const float* __restrict__ bih,
                     const float* __restrict__ bhh) {
    int tid = threadIdx.x, lane = tid & 31, warp = tid >> 5;
    int row = blockIdx.x*8 + warp;
    float wr[16];
    const float* w = Wih + (size_t)row*HID + lane*16;
    #pragma unroll
    for (int i = 0; i < 16; i++) wr[i] = w[i];
    float bsum = bih[row] + bhh[row];
    __shared__ float xs[HID];
    for (int b = 0; b < BATCH; b++) {
        __syncthreads();
        for (int i = tid; i < HID; i += 256) xs[i] = g_x[b*HID + i];
        __syncthreads();
        float a = 0.f;
        #pragma unroll
        for (int i = 0; i < 16; i++) a = fmaf(wr[i], xs[lane*16 + i], a);
        #pragma unroll
        for (int o = 16; o > 0; o >>= 1) a += __shfl_xor_sync(0xffffffffu, a, o);
        if (lane == 0) g_A0[b*G4 + row] = a + bsum;
    }
}

// ---------------- K_LSTM: persistent, two pipelined groups ------------------
// R1 skeleton (counter flags + single-lane poll + smem staging) with:
//  - red.release / ld.acquire instead of threadfence (no L1 flush)
//  - 2 syncthreads per step (stage bar -> __syncwarp; staging is warp-local)
//  - FFMA2 matvec, tanh.approx, tree reduction.
__global__ void __launch_bounds__(TPB, 1)
k_lstm(const float* __restrict__ Wih, const float* __restrict__ Whh,
       const float* __restrict__ bih, const float* __restrict__ bhh) {
    __shared__ float hbuf[2*HID];
    __shared__ float red[16*33];
    __shared__ float As[BATCH*32];
    __shared__ float bias1[32];
    const int tid = threadIdx.x, lane = tid & 31, warp = tid >> 5;
    const int gt = lane >> 3, j = lane & 7;
    float c_state = 0.f;

    if (blockIdx.x < N0) {
        // ===================== layer-0 group =====================
        const int g = blockIdx.x;
        const int grow = gt*HID + g*8 + j;
        unsigned long long w2[16];                 // 32 cols [warp*32,+32)
        {
            const ulonglong2* wp = (const ulonglong2*)(Whh + (size_t)grow*HID + warp*32);
            #pragma unroll
            for (int i = 0; i < 8; i++) { ulonglong2 v = wp[i]; w2[2*i] = v.x; w2[2*i+1] = v.y; }
        }
        for (int i = tid; i < BATCH*32; i += TPB) {
            int bb = i >> 5, lr = i & 31;
            As[i] = g_A0[bb*G4 + (lr>>3)*HID + g*8 + (lr&7)];
        }
        __syncthreads();

        for (int t = 0; t < TSTEPS; t++) {
            if (t > 0 && tid == 0) {
                while (ld_acq32(&g_flag0[t-1]) < N0) {}
            }
            __syncthreads();                                      // barA
            hbuf[warp*32 + lane] = (t == 0) ? 0.f
                                 : g_h0[(size_t)(t-1)*HID + warp*32 + lane];
            __syncwarp();
            unsigned long long a0 = 0ull, a1 = 0ull;
            const ulonglong2* hp = (const ulonglong2*)(hbuf + warp*32);
            #pragma unroll
            for (int i = 0; i < 8; i++) {
                ulonglong2 v = hp[i];
                a0 = fma2(w2[2*i],   v.x, a0);
                a1 = fma2(w2[2*i+1], v.y, a1);
            }
            red[warp*33 + lane] = fsum(a0) + fsum(a1);
            __syncthreads();                                      // barB
            if (warp == 0) {
                float s[16];
                #pragma unroll
                for (int ww = 0; ww < 16; ww++) s[ww] = red[ww*33 + lane];
                float q0 = (s[0]+s[1]) + (s[2]+s[3]);
                float q1 = (s[4]+s[5]) + (s[6]+s[7]);
                float q2 = (s[8]+s[9]) + (s[10]+s[11]);
                float q3 = (s[12]+s[13]) + (s[14]+s[15]);
                float gv = As[(t & (BATCH-1))*32 + lane] + ((q0+q1) + (q2+q3));
                float vi = __shfl_sync(0xffffffffu, gv, j);
                float vf = __shfl_sync(0xffffffffu, gv, 8 + j);
                float vg = __shfl_sync(0xffffffffu, gv, 16 + j);
                float vo = __shfl_sync(0xffffffffu, gv, 24 + j);
                if (lane < 8) {
                    c_state = sigf(vf)*c_state + sigf(vi)*tanhapx(vg);
                    g_h0[(size_t)t*HID + g*8 + lane] = sigf(vo)*tanhapx(c_state);
                }
                __syncwarp();
                if (lane == 0) red_rel_add(&g_flag0[t]);
            }
        }
    } else {
        // ===================== layer-1 group =====================
        const int g = blockIdx.x - N0;
        const int grow = gt*HID + g*8 + j;
        unsigned long long w2[32];                 // 64 cols [warp*64,+64) of [h0|h1]
        {
            const ulonglong2* wp = (warp < 8)
                ? (const ulonglong2*)(Wih + (size_t)G4*HID + (size_t)grow*HID + warp*64)
                : (const ulonglong2*)(Whh + (size_t)G4*HID + (size_t)grow*HID + (warp-8)*64);
            #pragma unroll
            for (int i = 0; i < 16; i++) { ulonglong2 v = wp[i]; w2[2*i] = v.x; w2[2*i+1] = v.y; }
        }
        if (tid < 32)
            bias1[tid] = bih[G4 + (tid>>3)*HID + g*8 + (tid&7)]
                       + bhh[G4 + (tid>>3)*HID + g*8 + (tid&7)];
        __syncthreads();

        for (int t = 0; t < TSTEPS; t++) {
            if (tid == 0) {
                while (ld_acq32(&g_flag0[t]) < N0) {}
                if (t > 0) while (ld_acq32(&g_flag1[t-1]) < N1) {}
            }
            __syncthreads();                                      // barA
            {
                float2 hv;
                if (warp < 8) {
                    hv = *(const float2*)(g_h0 + (size_t)t*HID + warp*64 + 2*lane);
                } else if (t > 0) {
                    hv = *(const float2*)(g_h1 + (size_t)(t-1)*HID + (warp-8)*64 + 2*lane);
                } else {
                    hv = make_float2(0.f, 0.f);
                }
                *(float2*)(hbuf + warp*64 + 2*lane) = hv;
            }
            __syncwarp();
            unsigned long long a0 = 0ull, a1 = 0ull, a2 = 0ull, a3 = 0ull;
            const ulonglong2* hp = (const ulonglong2*)(hbuf + warp*64);
            #pragma unroll
            for (int i = 0; i < 8; i++) {
                ulonglong2 v0 = hp[2*i], v1 = hp[2*i+1];
                a0 = fma2(w2[4*i],   v0.x, a0);
                a1 = fma2(w2[4*i+1], v0.y, a1);
                a2 = fma2(w2[4*i+2], v1.x, a2);
                a3 = fma2(w2[4*i+3], v1.y, a3);
            }
            red[warp*33 + lane] = (fsum(a0) + fsum(a1)) + (fsum(a2) + fsum(a3));
            __syncthreads();                                      // barB
            if (warp == 0) {
                float s[16];
                #pragma unroll
                for (int ww = 0; ww < 16; ww++) s[ww] = red[ww*33 + lane];
                float q0 = (s[0]+s[1]) + (s[2]+s[3]);
                float q1 = (s[4]+s[5]) + (s[6]+s[7]);
                float q2 = (s[8]+s[9]) + (s[10]+s[11]);
                float q3 = (s[12]+s[13]) + (s[14]+s[15]);
                float gv = bias1[lane] + ((q0+q1) + (q2+q3));
                float vi = __shfl_sync(0xffffffffu, gv, j);
                float vf = __shfl_sync(0xffffffffu, gv, 8 + j);
                float vg = __shfl_sync(0xffffffffu, gv, 16 + j);
                float vo = __shfl_sync(0xffffffffu, gv, 24 + j);
                if (lane < 8) {
                    c_state = sigf(vf)*c_state + sigf(vi)*tanhapx(vg);
                    g_h1[(size_t)t*HID + g*8 + lane] = sigf(vo)*tanhapx(c_state);
                }
                __syncwarp();
                if (lane == 0) red_rel_add(&g_flag1[t]);
            }
        }
    }
}

// ---------------- K3: final FC + tanh ---------------------------------------
__global__ void k_fc(const float* __restrict__ Wfc, const float* __restrict__ bfc,
                     float* __restrict__ out) {
    int s = blockIdx.x;
    int tid = threadIdx.x, lane = tid & 31, a = tid >> 5;
    int tt = s >> 7, b = s & 127;
    const float* h = g_h1 + (size_t)s*HID;
    const float* w = Wfc + a*HID;
    float acc = 0.f;
    for (int k = lane; k < HID; k += 32) acc = fmaf(h[k], w[k], acc);
    #pragma unroll
    for (int o = 16; o > 0; o >>= 1) acc += __shfl_xor_sync(0xffffffffu, acc, o);
    if (lane == 0) out[b*(SEQ*ACT) + tt*ACT + a] = tanhf(acc + bfc[a]);
}

// ---------------------------------------------------------------------------
extern "C" void kernel_launch(void* const* d_in, const int* in_sizes, int n_in,
                              void* d_out, int out_size) {
    const float* state = (const float*)d_in[0];
    const float* lng   = (const float*)d_in[1];
    const float* lnb   = (const float*)d_in[2];
    const float* Wpre  = (const float*)d_in[3];
    const float* bpre  = (const float*)d_in[4];
    const float* Wih   = (const float*)d_in[5];
    const float* Whh   = (const float*)d_in[6];
    const float* bih   = (const float*)d_in[7];
    const float* bhh   = (const float*)d_in[8];
    const float* Wfc   = (const float*)d_in[9];
    const float* bfc   = (const float*)d_in[10];
    float* out = (float*)d_out;

    k_init<<<(TSTEPS+255)/256, 256>>>();
    k_pre <<<BATCH, TPB>>>(state, lng, lnb, Wpre, bpre);
    k_a0  <<<G4/8, 256>>>(Wih, bih, bhh);
    k_lstm<<<NCTA, TPB>>>(Wih, Whh, bih, bhh);
    k_fc  <<<TSTEPS, 256>>>(Wfc, bfc, out);
}

// round 7
// speedup vs baseline: 10.0857x; 1.6802x over previous
#include <cuda_runtime.h>
#include <math.h>

#define STATE_DIM 64
#define HID 512
#define ACT 8
#define BATCH 128
#define SEQ 16
#define TSTEPS (SEQ*BATCH)   // 2048 sequential LSTM steps
#define G4 (4*HID)
#define N0 64
#define N1 64
#define NCTA (N0+N1)
#define TPB 512
#define SENT 0x7FBFFFFFu     // NaN payload: impossible h bit pattern

// ---------------- scratch ---------------------------------------------------
__device__ float g_x [BATCH*HID];
__device__ float g_A0[BATCH*G4];
__device__ float g_h0[TSTEPS*HID];
__device__ float g_h1[TSTEPS*HID];

// ---------------- helpers ---------------------------------------------------
__device__ __forceinline__ float tanhapx(float x) {
    float y; asm("tanh.approx.f32 %0, %1;" : "=f"(y) : "f"(x)); return y;
}
__device__ __forceinline__ float sigf(float x) { return 0.5f*tanhapx(0.5f*x) + 0.5f; }

__device__ __forceinline__ uint4 ldvol4(const uint4* p) {
    uint4 v;
    asm volatile("ld.volatile.global.v4.u32 {%0,%1,%2,%3}, [%4];"
                 : "=r"(v.x), "=r"(v.y), "=r"(v.z), "=r"(v.w) : "l"(p) : "memory");
    return v;
}
__device__ __forceinline__ int okv(uint4 v) {
    return (v.x != SENT) & (v.y != SENT) & (v.z != SENT) & (v.w != SENT);
}
__device__ __forceinline__ void stvolf(float* p, float v) {
    asm volatile("st.volatile.global.f32 [%0], %1;" :: "l"(p), "f"(v) : "memory");
}
__device__ __forceinline__ unsigned long long fma2(unsigned long long a,
                                                   unsigned long long b,
                                                   unsigned long long c) {
    unsigned long long d;
    asm("fma.rn.f32x2 %0, %1, %2, %3;" : "=l"(d) : "l"(a), "l"(b), "l"(c));
    return d;
}
__device__ __forceinline__ float fsum(unsigned long long v) {
    float x, y;
    asm("mov.b64 {%0,%1}, %2;" : "=f"(x), "=f"(y) : "l"(v));
    return x + y;
}

// Poller: wait for 256 floats (64 uint4) starting at src, stage to smem dst.
__device__ __forceinline__ void poll_stage(const float* src, float* dst, int lane) {
    const uint4* p = (const uint4*)src + lane;          // floats [4*lane, +4)
    uint4 a = ldvol4(p), b = ldvol4(p + 32);            // and [128+4*lane, +4)
    while (!__all_sync(0xffffffffu, okv(a) & okv(b))) {
        a = ldvol4(p); b = ldvol4(p + 32);
    }
    ((uint4*)dst)[lane]      = a;
    ((uint4*)dst)[32 + lane] = b;
}

// ---------------- K0: sentinel-fill h histories (graph replays) -------------
__global__ void k_init() {
    unsigned i = blockIdx.x*blockDim.x + threadIdx.x;   // 1024*256 = 262144
    uint4 s = make_uint4(SENT, SENT, SENT, SENT);
    ((uint4*)g_h0)[i] = s;
    ((uint4*)g_h1)[i] = s;
}

// ---------------- K1: LayerNorm + pre-linear --------------------------------
__global__ void k_pre(const float* __restrict__ state, const float* __restrict__ lng,
                      const float* __restrict__ lnb,   const float* __restrict__ Wpre,
                      const float* __restrict__ bpre) {
    __shared__ float xn[STATE_DIM];
    __shared__ float stats[2];
    int b = blockIdx.x, tid = threadIdx.x;
    if (tid < STATE_DIM) xn[tid] = state[b*STATE_DIM + tid];
    __syncthreads();
    if (tid == 0) {
        float mu = 0.f;
        for (int k = 0; k < STATE_DIM; k++) mu += xn[k];
        mu *= (1.f/STATE_DIM);
        float var = 0.f;
        for (int k = 0; k < STATE_DIM; k++) { float d = xn[k]-mu; var += d*d; }
        var *= (1.f/STATE_DIM);
        stats[0] = mu; stats[1] = rsqrtf(var + 1e-5f);
    }
    __syncthreads();
    float mu = stats[0], rs = stats[1];
    if (tid < STATE_DIM) xn[tid] = (xn[tid]-mu)*rs*lng[tid] + lnb[tid];
    __syncthreads();
    float acc = bpre[tid];
    const float* w = Wpre + tid*STATE_DIM;
    #pragma unroll 16
    for (int k = 0; k < STATE_DIM; k++) acc = fmaf(w[k], xn[k], acc);
    g_x[b*HID + tid] = acc;
}

// ---------------- K2: A0 = W_ih0@x + b_ih0 + b_hh0 --------------------------
__global__ void k_a0(const float* __restrict__ Wih, const float* __restrict__ bih,
                     const float* __restrict__ bhh) {
    int tid = threadIdx.x, lane = tid & 31, warp = tid >> 5;
    int row = blockIdx.x*8 + warp;
    float wr[16];
    const float* w = Wih + (size_t)row*HID + lane*16;
    #pragma unroll
    for (int i = 0; i < 16; i++) wr[i] = w[i];
    float bsum = bih[row] + bhh[row];
    __shared__ float xs[HID];
    for (int b = 0; b < BATCH; b++) {
        __syncthreads();
        for (int i = tid; i < HID; i += 256) xs[i] = g_x[b*HID + i];
        __syncthreads();
        float a = 0.f;
        #pragma unroll
        for (int i = 0; i < 16; i++) a = fmaf(wr[i], xs[lane*16 + i], a);
        #pragma unroll
        for (int o = 16; o > 0; o >>= 1) a += __shfl_xor_sync(0xffffffffu, a, o);
        if (lane == 0) g_A0[b*G4 + row] = a + bsum;
    }
}

// ---------------- K_LSTM: persistent, self-validating dataflow --------------
// No flags. Sentinel-prefilled h histories; designated poller warps (1..2 for
// layer-0, 1..4 for layer-1) poll+stage their 256-float span; warp 0 does the
// cell tail only. Two __syncthreads per step, exactly the R4 skeleton.
__global__ void __launch_bounds__(TPB, 1)
k_lstm(const float* __restrict__ Wih, const float* __restrict__ Whh,
       const float* __restrict__ bih, const float* __restrict__ bhh) {
    __shared__ float hbuf[2*HID];
    __shared__ float red[16*33];
    __shared__ float As[BATCH*32];
    __shared__ float bias1[32];
    const int tid = threadIdx.x, lane = tid & 31, warp = tid >> 5;
    const int gt = lane >> 3, j = lane & 7;
    float c_state = 0.f;

    if (blockIdx.x < N0) {
        // ===================== layer-0 group =====================
        const int g = blockIdx.x;
        const int grow = gt*HID + g*8 + j;
        unsigned long long w2[16];                 // 32 cols [warp*32,+32)
        {
            const ulonglong2* wp = (const ulonglong2*)(Whh + (size_t)grow*HID + warp*32);
            #pragma unroll
            for (int i = 0; i < 8; i++) { ulonglong2 v = wp[i]; w2[2*i] = v.x; w2[2*i+1] = v.y; }
        }
        for (int i = tid; i < BATCH*32; i += TPB) {
            int bb = i >> 5, lr = i & 31;
            As[i] = g_A0[bb*G4 + (lr>>3)*HID + g*8 + (lr&7)];
        }
        __syncthreads();

        for (int t = 0; t < TSTEPS; t++) {
            if (warp == 1 || warp == 2) {          // pollers/stagers
                float* dst = hbuf + (warp-1)*256;
                if (t > 0) {
                    poll_stage(g_h0 + (size_t)(t-1)*HID + (warp-1)*256, dst, lane);
                } else {
                    ((uint4*)dst)[lane]      = make_uint4(0,0,0,0);
                    ((uint4*)dst)[32 + lane] = make_uint4(0,0,0,0);
                }
            }
            __syncthreads();                                      // barA
            unsigned long long a0 = 0ull, a1 = 0ull;
            const ulonglong2* hp2 = (const ulonglong2*)(hbuf + warp*32);
            #pragma unroll
            for (int i = 0; i < 8; i++) {
                ulonglong2 v = hp2[i];
                a0 = fma2(w2[2*i],   v.x, a0);
                a1 = fma2(w2[2*i+1], v.y, a1);
            }
            red[warp*33 + lane] = fsum(a0) + fsum(a1);
            __syncthreads();                                      // barB
            if (warp == 0) {
                float s[16];
                #pragma unroll
                for (int ww = 0; ww < 16; ww++) s[ww] = red[ww*33 + lane];
                float q0 = (s[0]+s[1]) + (s[2]+s[3]);
                float q1 = (s[4]+s[5]) + (s[6]+s[7]);
                float q2 = (s[8]+s[9]) + (s[10]+s[11]);
                float q3 = (s[12]+s[13]) + (s[14]+s[15]);
                float gv = As[(t & (BATCH-1))*32 + lane] + ((q0+q1) + (q2+q3));
                float vi = __shfl_sync(0xffffffffu, gv, j);
                float vf = __shfl_sync(0xffffffffu, gv, 8 + j);
                float vg = __shfl_sync(0xffffffffu, gv, 16 + j);
                float vo = __shfl_sync(0xffffffffu, gv, 24 + j);
                if (lane < 8) {
                    c_state = sigf(vf)*c_state + sigf(vi)*tanhapx(vg);
                    stvolf(g_h0 + (size_t)t*HID + g*8 + lane, sigf(vo)*tanhapx(c_state));
                }
            }
        }
    } else {
        // ===================== layer-1 group =====================
        const int g = blockIdx.x - N0;
        const int grow = gt*HID + g*8 + j;
        unsigned long long w2[32];                 // 64 cols [warp*64,+64) of [h0|h1]
        {
            const ulonglong2* wp = (warp < 8)
                ? (const ulonglong2*)(Wih + (size_t)G4*HID + (size_t)grow*HID + warp*64)
                : (const ulonglong2*)(Whh + (size_t)G4*HID + (size_t)grow*HID + (warp-8)*64);
            #pragma unroll
            for (int i = 0; i < 16; i++) { ulonglong2 v = wp[i]; w2[2*i] = v.x; w2[2*i+1] = v.y; }
        }
        if (tid < 32)
            bias1[tid] = bih[G4 + (tid>>3)*HID + g*8 + (tid&7)]
                       + bhh[G4 + (tid>>3)*HID + g*8 + (tid&7)];
        __syncthreads();

        for (int t = 0; t < TSTEPS; t++) {
            if (warp >= 1 && warp <= 4) {
                float* dst = hbuf + (warp-1)*256;
                if (warp <= 2) {                   // h0[t] halves (always needed)
                    poll_stage(g_h0 + (size_t)t*HID + (warp-1)*256, dst, lane);
                } else if (t > 0) {                // h1[t-1] halves
                    poll_stage(g_h1 + (size_t)(t-1)*HID + (warp-3)*256, dst, lane);
                } else {
                    ((uint4*)dst)[lane]      = make_uint4(0,0,0,0);
                    ((uint4*)dst)[32 + lane] = make_uint4(0,0,0,0);
                }
            }
            __syncthreads();                                      // barA
            unsigned long long a0 = 0ull, a1 = 0ull, a2 = 0ull, a3 = 0ull;
            const ulonglong2* hp2 = (const ulonglong2*)(hbuf + warp*64);
            #pragma unroll
            for (int i = 0; i < 8; i++) {
                ulonglong2 v0 = hp2[2*i], v1 = hp2[2*i+1];
                a0 = fma2(w2[4*i],   v0.x, a0);
                a1 = fma2(w2[4*i+1], v0.y, a1);
                a2 = fma2(w2[4*i+2], v1.x, a2);
                a3 = fma2(w2[4*i+3], v1.y, a3);
            }
            red[warp*33 + lane] = (fsum(a0) + fsum(a1)) + (fsum(a2) + fsum(a3));
            __syncthreads();                                      // barB
            if (warp == 0) {
                float s[16];
                #pragma unroll
                for (int ww = 0; ww < 16; ww++) s[ww] = red[ww*33 + lane];
                float q0 = (s[0]+s[1]) + (s[2]+s[3]);
                float q1 = (s[4]+s[5]) + (s[6]+s[7]);
                float q2 = (s[8]+s[9]) + (s[10]+s[11]);
                float q3 = (s[12]+s[13]) + (s[14]+s[15]);
                float gv = bias1[lane] + ((q0+q1) + (q2+q3));
                float vi = __shfl_sync(0xffffffffu, gv, j);
                float vf = __shfl_sync(0xffffffffu, gv, 8 + j);
                float vg = __shfl_sync(0xffffffffu, gv, 16 + j);
                float vo = __shfl_sync(0xffffffffu, gv, 24 + j);
                if (lane < 8) {
                    c_state = sigf(vf)*c_state + sigf(vi)*tanhapx(vg);
                    stvolf(g_h1 + (size_t)t*HID + g*8 + lane, sigf(vo)*tanhapx(c_state));
                }
            }
        }
    }
}

// ---------------- K3: final FC + tanh ---------------------------------------
__global__ void k_fc(const float* __restrict__ Wfc, const float* __restrict__ bfc,
                     float* __restrict__ out) {
    int s = blockIdx.x;
    int tid = threadIdx.x, lane = tid & 31, a = tid >> 5;
    int tt = s >> 7, b = s & 127;
    const float* h = g_h1 + (size_t)s*HID;
    const float* w = Wfc + a*HID;
    float acc = 0.f;
    for (int k = lane; k < HID; k += 32) acc = fmaf(h[k], w[k], acc);
    #pragma unroll
    for (int o = 16; o > 0; o >>= 1) acc += __shfl_xor_sync(0xffffffffu, acc, o);
    if (lane == 0) out[b*(SEQ*ACT) + tt*ACT + a] = tanhf(acc + bfc[a]);
}

// ---------------------------------------------------------------------------
extern "C" void kernel_launch(void* const* d_in, const int* in_sizes, int n_in,
                              void* d_out, int out_size) {
    const float* state = (const float*)d_in[0];
    const float* lng   = (const float*)d_in[1];
    const float* lnb   = (const float*)d_in[2];
    const float* Wpre  = (const float*)d_in[3];
    const float* bpre  = (const float*)d_in[4];
    const float* Wih   = (const float*)d_in[5];
    const float* Whh   = (const float*)d_in[6];
    const float* bih   = (const float*)d_in[7];
    const float* bhh   = (const float*)d_in[8];
    const float* Wfc   = (const float*)d_in[9];
    const float* bfc   = (const float*)d_in[10];
    float* out = (float*)d_out;

    k_init<<<1024, 256>>>();
    k_pre <<<BATCH, TPB>>>(state, lng, lnb, Wpre, bpre);
    k_a0  <<<G4/8, 256>>>(Wih, bih, bhh);
    k_lstm<<<NCTA, TPB>>>(Wih, Whh, bih, bhh);
    k_fc  <<<TSTEPS, 256>>>(Wfc, bfc, out);
}

// round 8
// speedup vs baseline: 12.5789x; 1.2472x over previous
#include <cuda_runtime.h>
#include <math.h>

#define STATE_DIM 64
#define HID 512
#define ACT 8
#define BATCH 128
#define SEQ 16
#define TSTEPS (SEQ*BATCH)   // 2048 sequential LSTM steps
#define G4 (4*HID)
#define N0 64
#define N1 64
#define NCTA (N0+N1)
#define TPB 512
#define SENT 0x7FBFFFFFu     // NaN payload: impossible h bit pattern

// ---------------- scratch ---------------------------------------------------
__device__ float g_x [BATCH*HID];
__device__ float g_A0[BATCH*G4];
__device__ float g_h0[TSTEPS*HID];
__device__ float g_h1[TSTEPS*HID];

// ---------------- helpers ---------------------------------------------------
__device__ __forceinline__ float tanhapx(float x) {
    float y; asm("tanh.approx.f32 %0, %1;" : "=f"(y) : "f"(x)); return y;
}
__device__ __forceinline__ float sigf(float x) { return 0.5f*tanhapx(0.5f*x) + 0.5f; }

__device__ __forceinline__ unsigned ldvol32(const unsigned* p) {
    unsigned v;
    asm volatile("ld.volatile.global.u32 %0, [%1];" : "=r"(v) : "l"(p) : "memory");
    return v;
}
__device__ __forceinline__ uint2 ldvol64(const uint2* p) {
    uint2 v;
    asm volatile("ld.volatile.global.v2.u32 {%0,%1}, [%2];"
                 : "=r"(v.x), "=r"(v.y) : "l"(p) : "memory");
    return v;
}
__device__ __forceinline__ void stvolf(float* p, float v) {
    asm volatile("st.volatile.global.f32 [%0], %1;" :: "l"(p), "f"(v) : "memory");
}
__device__ __forceinline__ unsigned long long fma2(unsigned long long a,
                                                   unsigned long long b,
                                                   unsigned long long c) {
    unsigned long long d;
    asm("fma.rn.f32x2 %0, %1, %2, %3;" : "=l"(d) : "l"(a), "l"(b), "l"(c));
    return d;
}
__device__ __forceinline__ float fsum(unsigned long long v) {
    float x, y;
    asm("mov.b64 {%0,%1}, %2;" : "=f"(x), "=f"(y) : "l"(v));
    return x + y;
}

// ---------------- K0: sentinel-fill h histories (graph replays) -------------
__global__ void k_init() {
    unsigned i = blockIdx.x*blockDim.x + threadIdx.x;   // 1024*256 = 262144
    uint4 s = make_uint4(SENT, SENT, SENT, SENT);
    ((uint4*)g_h0)[i] = s;
    ((uint4*)g_h1)[i] = s;
}

// ---------------- K1: LayerNorm + pre-linear --------------------------------
__global__ void k_pre(const float* __restrict__ state, const float* __restrict__ lng,
                      const float* __restrict__ lnb,   const float* __restrict__ Wpre,
                      const float* __restrict__ bpre) {
    __shared__ float xn[STATE_DIM];
    __shared__ float stats[2];
    int b = blockIdx.x, tid = threadIdx.x;
    if (tid < STATE_DIM) xn[tid] = state[b*STATE_DIM + tid];
    __syncthreads();
    if (tid == 0) {
        float mu = 0.f;
        for (int k = 0; k < STATE_DIM; k++) mu += xn[k];
        mu *= (1.f/STATE_DIM);
        float var = 0.f;
        for (int k = 0; k < STATE_DIM; k++) { float d = xn[k]-mu; var += d*d; }
        var *= (1.f/STATE_DIM);
        stats[0] = mu; stats[1] = rsqrtf(var + 1e-5f);
    }
    __syncthreads();
    float mu = stats[0], rs = stats[1];
    if (tid < STATE_DIM) xn[tid] = (xn[tid]-mu)*rs*lng[tid] + lnb[tid];
    __syncthreads();
    float acc = bpre[tid];
    const float* w = Wpre + tid*STATE_DIM;
    #pragma unroll 16
    for (int k = 0; k < STATE_DIM; k++) acc = fmaf(w[k], xn[k], acc);
    g_x[b*HID + tid] = acc;
}

// ---------------- K2: A0 = W_ih0@x + b_ih0 + b_hh0 --------------------------
__global__ void k_a0(const float* __restrict__ Wih, const float* __restrict__ bih,
                     const float* __restrict__ bhh) {
    int tid = threadIdx.x, lane = tid & 31, warp = tid >> 5;
    int row = blockIdx.x*8 + warp;
    float wr[16];
    const float* w = Wih + (size_t)row*HID + lane*16;
    #pragma unroll
    for (int i = 0; i < 16; i++) wr[i] = w[i];
    float bsum = bih[row] + bhh[row];
    __shared__ float xs[HID];
    for (int b = 0; b < BATCH; b++) {
        __syncthreads();
        for (int i = tid; i < HID; i += 256) xs[i] = g_x[b*HID + i];
        __syncthreads();
        float a = 0.f;
        #pragma unroll
        for (int i = 0; i < 16; i++) a = fmaf(wr[i], xs[lane*16 + i], a);
        #pragma unroll
        for (int o = 16; o > 0; o >>= 1) a += __shfl_xor_sync(0xffffffffu, a, o);
        if (lane == 0) g_A0[b*G4 + row] = a + bsum;
    }
}

// ---------------- K_LSTM: persistent, self-validating dataflow --------------
// Each compute warp polls+stages its OWN h slice (volatile, sentinel-checked),
// so the pre-FFMA barrier is just __syncwarp. One __syncthreads (barB) per
// step before warp 0's cell tail.
__global__ void __launch_bounds__(TPB, 1)
k_lstm(const float* __restrict__ Wih, const float* __restrict__ Whh,
       const float* __restrict__ bih, const float* __restrict__ bhh) {
    __shared__ float hbuf[2*HID];
    __shared__ float red[16*33];
    __shared__ float As[BATCH*32];
    __shared__ float bias1[32];
    const int tid = threadIdx.x, lane = tid & 31, warp = tid >> 5;
    const int gt = lane >> 3, j = lane & 7;
    float c_state = 0.f;

    if (blockIdx.x < N0) {
        // ===================== layer-0 group =====================
        const int g = blockIdx.x;
        const int grow = gt*HID + g*8 + j;
        unsigned long long w2[16];                 // 32 cols [warp*32,+32)
        {
            const ulonglong2* wp = (const ulonglong2*)(Whh + (size_t)grow*HID + warp*32);
            #pragma unroll
            for (int i = 0; i < 8; i++) { ulonglong2 v = wp[i]; w2[2*i] = v.x; w2[2*i+1] = v.y; }
        }
        for (int i = tid; i < BATCH*32; i += TPB) {
            int bb = i >> 5, lr = i & 31;
            As[i] = g_A0[bb*G4 + (lr>>3)*HID + g*8 + (lr&7)];
        }
        __syncthreads();

        for (int t = 0; t < TSTEPS; t++) {
            // each warp polls + stages its own 32-col slice (1 float/lane)
            if (t > 0) {
                const unsigned* p =
                    (const unsigned*)(g_h0 + (size_t)(t-1)*HID + warp*32) + lane;
                unsigned v = ldvol32(p);
                while (!__all_sync(0xffffffffu, v != SENT)) v = ldvol32(p);
                hbuf[warp*32 + lane] = __uint_as_float(v);
            } else {
                hbuf[warp*32 + lane] = 0.f;
            }
            __syncwarp();
            unsigned long long a0 = 0ull, a1 = 0ull;
            const ulonglong2* hp2 = (const ulonglong2*)(hbuf + warp*32);
            #pragma unroll
            for (int i = 0; i < 8; i++) {
                ulonglong2 v = hp2[i];
                a0 = fma2(w2[2*i],   v.x, a0);
                a1 = fma2(w2[2*i+1], v.y, a1);
            }
            red[warp*33 + lane] = fsum(a0) + fsum(a1);
            __syncthreads();                                      // barB
            if (warp == 0) {
                float s[16];
                #pragma unroll
                for (int ww = 0; ww < 16; ww++) s[ww] = red[ww*33 + lane];
                float q0 = (s[0]+s[1]) + (s[2]+s[3]);
                float q1 = (s[4]+s[5]) + (s[6]+s[7]);
                float q2 = (s[8]+s[9]) + (s[10]+s[11]);
                float q3 = (s[12]+s[13]) + (s[14]+s[15]);
                float gv = As[(t & (BATCH-1))*32 + lane] + ((q0+q1) + (q2+q3));
                float vi = __shfl_sync(0xffffffffu, gv, j);
                float vf = __shfl_sync(0xffffffffu, gv, 8 + j);
                float vg = __shfl_sync(0xffffffffu, gv, 16 + j);
                float vo = __shfl_sync(0xffffffffu, gv, 24 + j);
                if (lane < 8) {
                    c_state = sigf(vf)*c_state + sigf(vi)*tanhapx(vg);
                    stvolf(g_h0 + (size_t)t*HID + g*8 + lane, sigf(vo)*tanhapx(c_state));
                }
            }
        }
    } else {
        // ===================== layer-1 group =====================
        const int g = blockIdx.x - N0;
        const int grow = gt*HID + g*8 + j;
        unsigned long long w2[32];                 // 64 cols [warp*64,+64) of [h0|h1]
        {
            const ulonglong2* wp = (warp < 8)
                ? (const ulonglong2*)(Wih + (size_t)G4*HID + (size_t)grow*HID + warp*64)
                : (const ulonglong2*)(Whh + (size_t)G4*HID + (size_t)grow*HID + (warp-8)*64);
            #pragma unroll
            for (int i = 0; i < 16; i++) { ulonglong2 v = wp[i]; w2[2*i] = v.x; w2[2*i+1] = v.y; }
        }
        if (tid < 32)
            bias1[tid] = bih[G4 + (tid>>3)*HID + g*8 + (tid&7)]
                       + bhh[G4 + (tid>>3)*HID + g*8 + (tid&7)];
        __syncthreads();

        for (int t = 0; t < TSTEPS; t++) {
            // each warp polls + stages its own 64-col slice (2 floats/lane)
            if (warp < 8) {                        // h0[t]: produced ahead, cheap poll
                const uint2* p =
                    (const uint2*)(g_h0 + (size_t)t*HID + warp*64) + lane;
                uint2 v = ldvol64(p);
                while (!__all_sync(0xffffffffu, (v.x != SENT) & (v.y != SENT)))
                    v = ldvol64(p);
                *(float2*)(hbuf + warp*64 + 2*lane) =
                    make_float2(__uint_as_float(v.x), __uint_as_float(v.y));
            } else if (t > 0) {                    // h1[t-1]: the recurrence
                const uint2* p =
                    (const uint2*)(g_h1 + (size_t)(t-1)*HID + (warp-8)*64) + lane;
                uint2 v = ldvol64(p);
                while (!__all_sync(0xffffffffu, (v.x != SENT) & (v.y != SENT)))
                    v = ldvol64(p);
                *(float2*)(hbuf + warp*64 + 2*lane) =
                    make_float2(__uint_as_float(v.x), __uint_as_float(v.y));
            } else {
                *(float2*)(hbuf + warp*64 + 2*lane) = make_float2(0.f, 0.f);
            }
            __syncwarp();
            unsigned long long a0 = 0ull, a1 = 0ull, a2 = 0ull, a3 = 0ull;
            const ulonglong2* hp2 = (const ulonglong2*)(hbuf + warp*64);
            #pragma unroll
            for (int i = 0; i < 8; i++) {
                ulonglong2 v0 = hp2[2*i], v1 = hp2[2*i+1];
                a0 = fma2(w2[4*i],   v0.x, a0);
                a1 = fma2(w2[4*i+1], v0.y, a1);
                a2 = fma2(w2[4*i+2], v1.x, a2);
                a3 = fma2(w2[4*i+3], v1.y, a3);
            }
            red[warp*33 + lane] = (fsum(a0) + fsum(a1)) + (fsum(a2) + fsum(a3));
            __syncthreads();                                      // barB
            if (warp == 0) {
                float s[16];
                #pragma unroll
                for (int ww = 0; ww < 16; ww++) s[ww] = red[ww*33 + lane];
                float q0 = (s[0]+s[1]) + (s[2]+s[3]);
                float q1 = (s[4]+s[5]) + (s[6]+s[7]);
                float q2 = (s[8]+s[9]) + (s[10]+s[11]);
                float q3 = (s[12]+s[13]) + (s[14]+s[15]);
                float gv = bias1[lane] + ((q0+q1) + (q2+q3));
                float vi = __shfl_sync(0xffffffffu, gv, j);
                float vf = __shfl_sync(0xffffffffu, gv, 8 + j);
                float vg = __shfl_sync(0xffffffffu, gv, 16 + j);
                float vo = __shfl_sync(0xffffffffu, gv, 24 + j);
                if (lane < 8) {
                    c_state = sigf(vf)*c_state + sigf(vi)*tanhapx(vg);
                    stvolf(g_h1 + (size_t)t*HID + g*8 + lane, sigf(vo)*tanhapx(c_state));
                }
            }
        }
    }
}

// ---------------- K3: final FC + tanh ---------------------------------------
__global__ void k_fc(const float* __restrict__ Wfc, const float* __restrict__ bfc,
                     float* __restrict__ out) {
    int s = blockIdx.x;
    int tid = threadIdx.x, lane = tid & 31, a = tid >> 5;
    int tt = s >> 7, b = s & 127;
    const float* h = g_h1 + (size_t)s*HID;
    const float* w = Wfc + a*HID;
    float acc = 0.f;
    for (int k = lane; k < HID; k += 32) acc = fmaf(h[k], w[k], acc);
    #pragma unroll
    for (int o = 16; o > 0; o >>= 1) acc += __shfl_xor_sync(0xffffffffu, acc, o);
    if (lane == 0) out[b*(SEQ*ACT) + tt*ACT + a] = tanhf(acc + bfc[a]);
}

// ---------------------------------------------------------------------------
extern "C" void kernel_launch(void* const* d_in, const int* in_sizes, int n_in,
                              void* d_out, int out_size) {
    const float* state = (const float*)d_in[0];
    const float* lng   = (const float*)d_in[1];
    const float* lnb   = (const float*)d_in[2];
    const float* Wpre  = (const float*)d_in[3];
    const float* bpre  = (const float*)d_in[4];
    const float* Wih   = (const float*)d_in[5];
    const float* Whh   = (const float*)d_in[6];
    const float* bih   = (const float*)d_in[7];
    const float* bhh   = (const float*)d_in[8];
    const float* Wfc   = (const float*)d_in[9];
    const float* bfc   = (const float*)d_in[10];
    float* out = (float*)d_out;

    k_init<<<1024, 256>>>();
    k_pre <<<BATCH, TPB>>>(state, lng, lnb, Wpre, bpre);
    k_a0  <<<G4/8, 256>>>(Wih, bih, bhh);
    k_lstm<<<NCTA, TPB>>>(Wih, Whh, bih, bhh);
    k_fc  <<<TSTEPS, 256>>>(Wfc, bfc, out);
}